// round 16
// baseline (speedup 1.0000x reference)
#include <cuda_runtime.h>
#include <cuda_bf16.h>
#include <cstdint>

typedef unsigned long long u64;
typedef unsigned int       u32;
typedef unsigned short     u16;

// ---------------------------------------------------------------------------
// HandGNNEncoder, two-kernel pipeline:
//   Kernel A: xa = A_norm x (sparse, unrolled); q = pooled relu GCN layer 1,
//             stored to global scratch as split-bf16 (hi + residual lo).
//   Kernel B: out = q @ W2 + b2 via 3-pass split-bf16 mma.sync (m16n8k16).
// ---------------------------------------------------------------------------

#define R2f  0.70710678118654752440f
#define R3f  0.57735026918962576451f
#define T3f  (1.0f/3.0f)
#define W23f (R2f*R3f)

__constant__ float CCv[21] = {
    (1.0f + 2.0f*R2f + 3.0f*R3f)/21.0f,
    1.0f/21.0f, 1.0f/21.0f, 1.0f/21.0f, 0.5f/21.0f,
    (1.0f + W23f)/21.0f, 1.0f/21.0f, 1.0f/21.0f, 0.5f/21.0f,
    (2.0f/3.0f + W23f)/21.0f, 1.0f/21.0f, 1.0f/21.0f, 0.5f/21.0f,
    (2.0f/3.0f + W23f)/21.0f, 1.0f/21.0f, 1.0f/21.0f, 0.5f/21.0f,
    (1.0f/3.0f + W23f)/21.0f, 1.0f/21.0f, 1.0f/21.0f, 0.5f/21.0f
};

#define NGRAPHS 32768
#define TILE_G  64
#define NTILES  (NGRAPHS/TILE_G)      // 512

// global scratch: split-bf16 q, dense [tile][g(64)][d(64)] u16
__device__ __align__(16) u16 g_qh[NTILES * TILE_G * 64];
__device__ __align__(16) u16 g_ql[NTILES * TILE_G * 64];

__device__ __forceinline__ u32 smem_u32(const void* p) {
    u32 a;
    asm("{ .reg .u64 t; cvta.to.shared.u64 t, %1; cvt.u32.u64 %0, t; }"
        : "=r"(a) : "l"(p));
    return a;
}
__device__ __forceinline__ u64 packf2(float lo, float hi) {
    u64 r; asm("mov.b64 %0, {%1,%2};" : "=l"(r) : "f"(lo), "f"(hi)); return r;
}
__device__ __forceinline__ void unpackf2(u64 v, float& lo, float& hi) {
    asm("mov.b64 {%0,%1}, %2;" : "=f"(lo), "=f"(hi) : "l"(v));
}
__device__ __forceinline__ u64 fma2(u64 a, u64 b, u64 c) {
    u64 d; asm("fma.rn.f32x2 %0, %1, %2, %3;" : "=l"(d) : "l"(a), "l"(b), "l"(c));
    return d;
}
// result: lo half = bf16(a), hi half = bf16(b)
__device__ __forceinline__ u32 cvt_bf16x2(float a, float b) {
    u32 r; asm("cvt.rn.bf16x2.f32 %0, %1, %2;" : "=r"(r) : "f"(b), "f"(a));
    return r;
}
__device__ __forceinline__ void ldsm_x4(u32& r0, u32& r1, u32& r2, u32& r3, u32 a) {
    asm volatile("ldmatrix.sync.aligned.m8n8.x4.shared.b16 {%0,%1,%2,%3}, [%4];"
                 : "=r"(r0), "=r"(r1), "=r"(r2), "=r"(r3) : "r"(a));
}
__device__ __forceinline__ void ldsm_x2(u32& r0, u32& r1, u32 a) {
    asm volatile("ldmatrix.sync.aligned.m8n8.x2.shared.b16 {%0,%1}, [%2];"
                 : "=r"(r0), "=r"(r1) : "r"(a));
}
__device__ __forceinline__ void mma_bf16(float* c, const u32* a, const u32* b) {
    asm volatile("mma.sync.aligned.m16n8k16.row.col.f32.bf16.bf16.f32 "
                 "{%0,%1,%2,%3},{%4,%5,%6,%7},{%8,%9},{%0,%1,%2,%3};"
                 : "+f"(c[0]), "+f"(c[1]), "+f"(c[2]), "+f"(c[3])
                 : "r"(a[0]), "r"(a[1]), "r"(a[2]), "r"(a[3]),
                   "r"(b[0]), "r"(b[1]));
}

// ============================ Kernel A ====================================
__global__ void __launch_bounds__(128, 4)
gnn_qk_kernel(const float* __restrict__ x,   // [G,21,2]
              const float* __restrict__ W1,  // [2,64]
              const float* __restrict__ b1)  // [64]
{
    __shared__ float xa[2 * 21 * TILE_G];    // planes [k][s][g], plane=1344
    __shared__ u16 ah[TILE_G * 64];          // q hi, dense [g][d]
    __shared__ u16 al[TILE_G * 64];          // q lo

    const int t    = threadIdx.x;
    const int tile = blockIdx.x;
    const int g0   = tile * TILE_G;

    // ---- phase 1: per-thread sparse aggregation (t<64, graph = g0+t) ----
    if (t < TILE_G) {
        const float2* xp = (const float2*)x + (size_t)(g0 + t) * 21;
        float2 v[21];
#pragma unroll
        for (int s = 0; s < 21; ++s) v[s] = __ldg(&xp[s]);
        float2 a[21];
        a[0].x = v[0].x;                     a[0].y = v[0].y;
        a[1].x = 0.5f*v[1].x + R2f*v[0].x;   a[1].y = 0.5f*v[1].y + R2f*v[0].y;
        a[2].x = 0.5f*(v[2].x + v[1].x);     a[2].y = 0.5f*(v[2].y + v[1].y);
        a[3].x = 0.5f*(v[3].x + v[2].x);     a[3].y = 0.5f*(v[3].y + v[2].y);
        a[4].x = 0.5f*(v[4].x + v[3].x);     a[4].y = 0.5f*(v[4].y + v[3].y);
        a[5].x = 0.5f*v[5].x + R2f*v[0].x;   a[5].y = 0.5f*v[5].y + R2f*v[0].y;
        a[6].x = 0.5f*(v[6].x + v[5].x);     a[6].y = 0.5f*(v[6].y + v[5].y);
        a[7].x = 0.5f*(v[7].x + v[6].x);     a[7].y = 0.5f*(v[7].y + v[6].y);
        a[8].x = 0.5f*(v[8].x + v[7].x);     a[8].y = 0.5f*(v[8].y + v[7].y);
        a[9].x  = T3f*v[9].x + R3f*v[0].x + W23f*v[5].x;
        a[9].y  = T3f*v[9].y + R3f*v[0].y + W23f*v[5].y;
        a[10].x = 0.5f*v[10].x + W23f*v[9].x; a[10].y = 0.5f*v[10].y + W23f*v[9].y;
        a[11].x = 0.5f*(v[11].x + v[10].x);  a[11].y = 0.5f*(v[11].y + v[10].y);
        a[12].x = 0.5f*(v[12].x + v[11].x);  a[12].y = 0.5f*(v[12].y + v[11].y);
        a[13].x = T3f*v[13].x + R3f*v[0].x + T3f*v[9].x;
        a[13].y = T3f*v[13].y + R3f*v[0].y + T3f*v[9].y;
        a[14].x = 0.5f*v[14].x + W23f*v[13].x; a[14].y = 0.5f*v[14].y + W23f*v[13].y;
        a[15].x = 0.5f*(v[15].x + v[14].x);  a[15].y = 0.5f*(v[15].y + v[14].y);
        a[16].x = 0.5f*(v[16].x + v[15].x);  a[16].y = 0.5f*(v[16].y + v[15].y);
        a[17].x = T3f*v[17].x + R3f*v[0].x + T3f*v[13].x;
        a[17].y = T3f*v[17].y + R3f*v[0].y + T3f*v[13].y;
        a[18].x = 0.5f*v[18].x + W23f*v[17].x; a[18].y = 0.5f*v[18].y + W23f*v[17].y;
        a[19].x = 0.5f*(v[19].x + v[18].x);  a[19].y = 0.5f*(v[19].y + v[18].y);
        a[20].x = 0.5f*(v[20].x + v[19].x);  a[20].y = 0.5f*(v[20].y + v[19].y);
#pragma unroll
        for (int s = 0; s < 21; ++s) {
            xa[s * TILE_G + t]        = a[s].x;
            xa[1344 + s * TILE_G + t] = a[s].y;
        }
    }
    __syncthreads();

    // ---- phase 2: q over graph pairs (f32x2), split-bf16 into ah/al ----
    {
        const int d  = t & 63;                // hidden channel
        const int gq = t >> 6;                // 0/1: 32-graph block
        const u64 w0p = packf2(W1[d], W1[d]);
        const u64 w1p = packf2(W1[64 + d], W1[64 + d]);
        const u64 b1p = packf2(b1[d], b1[d]);
        u64 acc2[16];
#pragma unroll
        for (int j = 0; j < 16; ++j) acc2[j] = 0ull;

#pragma unroll
        for (int s = 0; s < 21; ++s) {
            const u64 ccp = packf2(CCv[s], CCv[s]);
            const int bo = s * TILE_G + 32 * gq;
#pragma unroll
            for (int h = 0; h < 2; ++h) {
                const ulonglong2 xA = *(const ulonglong2*)&xa[bo + 16*h];
                const ulonglong2 xB = *(const ulonglong2*)&xa[bo + 16*h + 4];
                const ulonglong2 xC = *(const ulonglong2*)&xa[bo + 16*h + 8];
                const ulonglong2 xD = *(const ulonglong2*)&xa[bo + 16*h + 12];
                const ulonglong2 yA = *(const ulonglong2*)&xa[1344 + bo + 16*h];
                const ulonglong2 yB = *(const ulonglong2*)&xa[1344 + bo + 16*h + 4];
                const ulonglong2 yC = *(const ulonglong2*)&xa[1344 + bo + 16*h + 8];
                const ulonglong2 yD = *(const ulonglong2*)&xa[1344 + bo + 16*h + 12];
#define PROC(xx, yy, idx) do {                                      \
    u64 _v = fma2((xx), w0p, fma2((yy), w1p, b1p));                 \
    float _a, _b; unpackf2(_v, _a, _b);                             \
    _a = fmaxf(_a, 0.0f); _b = fmaxf(_b, 0.0f);                     \
    acc2[idx] = fma2(packf2(_a, _b), ccp, acc2[idx]); } while (0)
                PROC(xA.x, yA.x, 8*h + 0);  PROC(xA.y, yA.y, 8*h + 1);
                PROC(xB.x, yB.x, 8*h + 2);  PROC(xB.y, yB.y, 8*h + 3);
                PROC(xC.x, yC.x, 8*h + 4);  PROC(xC.y, yC.y, 8*h + 5);
                PROC(xD.x, yD.x, 8*h + 6);  PROC(xD.y, yD.y, 8*h + 7);
#undef PROC
            }
        }
#pragma unroll
        for (int j = 0; j < 16; ++j) {
            float q0, q1; unpackf2(acc2[j], q0, q1);
            const u32 hh = cvt_bf16x2(q0, q1);          // graphs (g, g+1) at d
            const float f0 = __uint_as_float(hh << 16);
            const float f1 = __uint_as_float(hh & 0xffff0000u);
            const u32 ll = cvt_bf16x2(q0 - f0, q1 - f1);
            const int o = (32 * gq + 2 * j) * 64 + d;
            ah[o] = (u16)hh;  ah[o + 64] = (u16)(hh >> 16);
            al[o] = (u16)ll;  al[o + 64] = (u16)(ll >> 16);
        }
    }
    __syncthreads();

    // ---- coalesced copy-out: 8 KB per array = 512 uint4, 128 threads ----
    {
        const uint4* sh = (const uint4*)ah;
        const uint4* sl = (const uint4*)al;
        uint4* dh = (uint4*)(g_qh + (size_t)tile * TILE_G * 64);
        uint4* dl = (uint4*)(g_ql + (size_t)tile * TILE_G * 64);
#pragma unroll
        for (int i = 0; i < 4; ++i) {
            dh[t + 128 * i] = sh[t + 128 * i];
            dl[t + 128 * i] = sl[t + 128 * i];
        }
    }
}

// ============================ Kernel B ====================================
// smem layout (bytes): pitch-72 u16 rows (144B) -> conflict-free ldmatrix
#define SB_AH 0                       // 64*144  = 9216
#define SB_AL 9216
#define SB_BH 18432                   // 128*144 = 18432
#define SB_BL 36864
#define SB_B2 55296                   // 128 floats
#define SB_TOT 55808

__global__ void __launch_bounds__(256, 3)
gnn_gemm_kernel(const float* __restrict__ W2,  // [64,128]
                const float* __restrict__ b2,  // [128]
                float* __restrict__ out)       // [G,128]
{
    extern __shared__ char smem[];
    const int t    = threadIdx.x;
    const int tile = blockIdx.x;
    const int g0   = tile * TILE_G;

    // ---- stage B tiles: W2^T split bf16 hi/lo, [f-row][d-col], pitch 72 ----
    {
        u16* bh = (u16*)(smem + SB_BH);
        u16* bl = (u16*)(smem + SB_BL);
        for (int i = t; i < 64 * 128; i += 256) {
            const float w = W2[i];             // i = d*128 + f
            const int dd = i >> 7, ff = i & 127;
            __nv_bfloat16 hb = __float2bfloat16(w);
            const float hf = __bfloat162float(hb);
            __nv_bfloat16 lb = __float2bfloat16(w - hf);
            bh[ff * 72 + dd] = reinterpret_cast<u16&>(hb);
            bl[ff * 72 + dd] = reinterpret_cast<u16&>(lb);
        }
        if (t < 128) ((float*)(smem + SB_B2))[t] = b2[t];
    }

    // ---- stage A tiles from scratch: dense [g][64] -> pitch-72 rows ----
    {
        const uint4* sh = (const uint4*)(g_qh + (size_t)tile * TILE_G * 64);
        const uint4* sl = (const uint4*)(g_ql + (size_t)tile * TILE_G * 64);
#pragma unroll
        for (int i = 0; i < 2; ++i) {
            const int c   = t + 256 * i;       // 0..511 16B-chunks
            const int row = c >> 3, seg = c & 7;
            *(uint4*)(smem + SB_AH + row * 144 + seg * 16) = sh[c];
            *(uint4*)(smem + SB_AL + row * 144 + seg * 16) = sl[c];
        }
    }
    __syncthreads();

    // ---- 64x128x64 GEMM: 3 split passes of m16n8k16 bf16 ----
    const int wid  = t >> 5;
    const int lane = t & 31;
    const int m0 = (wid & 1) * 32;            // 32 graph rows per warp
    const int n0 = (wid >> 1) * 32;           // 32 feature cols per warp

    const u32 sbase = smem_u32(smem);
    const u32 aH = sbase + SB_AH + (m0 + (lane & 15)) * 144 + ((lane >> 4) << 4);
    const u32 aL = sbase + SB_AL + (m0 + (lane & 15)) * 144 + ((lane >> 4) << 4);
    const u32 bH = sbase + SB_BH + (n0 + (lane & 7)) * 144 + (((lane >> 3) & 1) << 4);
    const u32 bL = sbase + SB_BL + (n0 + (lane & 7)) * 144 + (((lane >> 3) & 1) << 4);

    float acc[2][4][4];
#pragma unroll
    for (int mt = 0; mt < 2; ++mt)
#pragma unroll
        for (int nt = 0; nt < 4; ++nt)
#pragma unroll
            for (int r = 0; r < 4; ++r) acc[mt][nt][r] = 0.0f;

#pragma unroll
    for (int kt = 0; kt < 4; ++kt) {
        u32 af[2][4];
#pragma unroll
        for (int mt = 0; mt < 2; ++mt)
            ldsm_x4(af[mt][0], af[mt][1], af[mt][2], af[mt][3],
                    aH + mt * (16 * 144) + kt * 32);
        u32 bf[4][2];
#pragma unroll
        for (int nt = 0; nt < 4; ++nt)
            ldsm_x2(bf[nt][0], bf[nt][1], bH + nt * (8 * 144) + kt * 32);
#pragma unroll
        for (int mt = 0; mt < 2; ++mt)
#pragma unroll
            for (int nt = 0; nt < 4; ++nt)
                mma_bf16(acc[mt][nt], af[mt], bf[nt]);
#pragma unroll
        for (int nt = 0; nt < 4; ++nt)
            ldsm_x2(bf[nt][0], bf[nt][1], bL + nt * (8 * 144) + kt * 32);
#pragma unroll
        for (int mt = 0; mt < 2; ++mt)
#pragma unroll
            for (int nt = 0; nt < 4; ++nt)
                mma_bf16(acc[mt][nt], af[mt], bf[nt]);
    }
#pragma unroll
    for (int kt = 0; kt < 4; ++kt) {          // pass 3: Al * Bh
        u32 af[2][4];
#pragma unroll
        for (int mt = 0; mt < 2; ++mt)
            ldsm_x4(af[mt][0], af[mt][1], af[mt][2], af[mt][3],
                    aL + mt * (16 * 144) + kt * 32);
        u32 bf[4][2];
#pragma unroll
        for (int nt = 0; nt < 4; ++nt)
            ldsm_x2(bf[nt][0], bf[nt][1], bH + nt * (8 * 144) + kt * 32);
#pragma unroll
        for (int mt = 0; mt < 2; ++mt)
#pragma unroll
            for (int nt = 0; nt < 4; ++nt)
                mma_bf16(acc[mt][nt], af[mt], bf[nt]);
    }

    // ---- epilogue: bias + store ----
    {
        const float* b2s = (const float*)(smem + SB_B2);
        const int r0 = m0 + (lane >> 2);
        const int c0 = n0 + 2 * (lane & 3);
#pragma unroll
        for (int mt = 0; mt < 2; ++mt) {
#pragma unroll
            for (int nt = 0; nt < 4; ++nt) {
                const int row = g0 + r0 + 16 * mt;
                const int col = c0 + 8 * nt;
                const float2 bb = *(const float2*)&b2s[col];
                float2 v0, v1;
                v0.x = acc[mt][nt][0] + bb.x;  v0.y = acc[mt][nt][1] + bb.y;
                v1.x = acc[mt][nt][2] + bb.x;  v1.y = acc[mt][nt][3] + bb.y;
                *(float2*)&out[(size_t)row * 128 + col] = v0;
                *(float2*)&out[(size_t)(row + 8) * 128 + col] = v1;
            }
        }
    }
}

extern "C" void kernel_launch(void* const* d_in, const int* in_sizes, int n_in,
                              void* d_out, int out_size)
{
    const float* x  = (const float*)d_in[0];  // hand_landmarks [64,512,21,2]
    const float* W1 = (const float*)d_in[1];  // [2,64]
    const float* b1 = (const float*)d_in[2];  // [64]
    const float* W2 = (const float*)d_in[3];  // [64,128]
    const float* b2 = (const float*)d_in[4];  // [128]
    float* out = (float*)d_out;               // [64,512,128]

    gnn_qk_kernel<<<NTILES, 128>>>(x, W1, b1);
    cudaFuncSetAttribute(gnn_gemm_kernel,
                         cudaFuncAttributeMaxDynamicSharedMemorySize, SB_TOT);
    gnn_gemm_kernel<<<NTILES, 256, SB_TOT>>>(W2, b2, out);
}